// round 14
// baseline (speedup 1.0000x reference)
#include <cuda_runtime.h>
#include <math.h>

#define NA 48
#define NB 24
#define DIM 286
#define NBATCH 256
#define NMU 6
#define L5OFF 165

typedef unsigned long long u64;

// f32x2 packed helpers (FFMA2 — PTX-only on sm_103a)
__device__ __forceinline__ u64 pack2(float lo, float hi) {
    u64 r; asm("mov.b64 %0, {%1, %2};" : "=l"(r) : "f"(lo), "f"(hi)); return r;
}
__device__ __forceinline__ void unpack2(u64 v, float& lo, float& hi) {
    asm("mov.b64 {%0, %1}, %2;" : "=f"(lo), "=f"(hi) : "l"(v));
}
__device__ __forceinline__ u64 fma2(u64 a, u64 b, u64 c) {
    u64 r; asm("fma.rn.f32x2 %0, %1, %2, %3;" : "=l"(r) : "l"(a), "l"(b), "l"(c)); return r;
}
__device__ __forceinline__ u64 add2(u64 a, u64 b) {
    u64 r; asm("add.rn.f32x2 %0, %1, %2;" : "=l"(r) : "l"(a), "l"(b)); return r;
}
__device__ __forceinline__ float ex2a(float x) {
    float r; asm("ex2.approx.f32 %0, %1;" : "=f"(r) : "f"(x)); return r;
}
__device__ __forceinline__ float rcpa(float x) {
    float r; asm("rcp.approx.f32 %0, %1;" : "=f"(r) : "f"(x)); return r;
}

// Scratch (static device globals; no allocation)
__device__ float g_c[NA * NMU];                // cos-like per (x, mu)
__device__ float g_s[NA * NMU];                // sin-like per (x, mu)
__device__ float g_act;                        // normalize2mom constant for tanh
__device__ float g_Q[NBATCH * NB * 144];       // Q forms [b][y][mn*4+c]

__constant__ int c_off[6] = {0, 1, 10, 35, 84, 165};

// ---------------------------------------------------------------------------
// Prep (merged): ACT_CST integral (20001-pt trapz, err ~1e-7 vs ref's 1e6-pt)
// + per-sector 2x2 alpha-rotation (c,s) from the l=5 block of D.
// Single CTA, 512 threads.
// ---------------------------------------------------------------------------
__global__ void prep_kernel(const float* __restrict__ D) {
    const float L2E2 = 2.8853900817779268f;  // 2*log2(e)
    int t = threadIdx.x;

    // --- activation integral ---
    float sum = 0.f;
    for (int i = t; i <= 20000; i += 512) {
        float x = -12.f + (float)i * 1.2e-3f;
        float th = 1.0f - 2.0f * rcpa(ex2a(x * L2E2) + 1.0f);
        sum += th * th * __expf(-0.5f * x * x);
    }
    for (int o = 16; o; o >>= 1) sum += __shfl_down_sync(0xffffffffu, sum, o);
    __shared__ float ws[16];
    if ((t & 31) == 0) ws[t >> 5] = sum;
    __syncthreads();
    if (t == 0) {
        float tot = 0.f;
        for (int i = 0; i < 16; i++) tot += ws[i];
        float I = tot * 1.2e-3f * 0.3989422804014327f;
        g_act = 1.0f / sqrtf(I);
    }

    // --- trig extraction: Ra5[x] = D5[x,0,0] * D5[0,0,0]^T / 11 ---
    if (t < NA * NMU) {
        int x = t / NMU, mu = t % NMU;
        int p0 = 5 - mu, p1 = 5 + mu;
        const float* X = D + (size_t)x * NB * NA * DIM + L5OFF;
        const float* Z = D + L5OFF;
        float a00 = 0.f, a01 = 0.f, a10 = 0.f, a11 = 0.f;
        for (int k = 0; k < 11; k++) {
            float xp0 = X[p0 * 11 + k], xp1 = X[p1 * 11 + k];
            float zp0 = Z[p0 * 11 + k], zp1 = Z[p1 * 11 + k];
            a00 += xp0 * zp0; a01 += xp0 * zp1;
            a10 += xp1 * zp0; a11 += xp1 * zp1;
        }
        const float inv11 = 1.f / 11.f;
        g_c[t] = 0.5f * (a00 + a11) * inv11;
        g_s[t] = 0.5f * (a01 - a10) * inv11;
    }
}

// ---------------------------------------------------------------------------
// Main (warp-autonomous, f32x2): grid (b, ys) x 128 threads. Warp w handles
// y = ys*4 + w. P (K-prescaled, stored as pre-splatted u64 pairs) ->
// T (broadcast LDS, no packs) -> fused synth+tanh+U -> Q.
// Lane owns z0=lane, z1=32+(lane&15).
// ---------------------------------------------------------------------------
__global__ __launch_bounds__(128) void so3_main(const float* __restrict__ feat,
                                                const float* __restrict__ D,
                                                const float* __restrict__ qw) {
    const int b = blockIdx.x;
    const int t = threadIdx.x;
    const int w = t >> 5;
    const int lane = t & 31;
    const int y = blockIdx.y * 4 + w;

    __shared__ float sF[DIM];
    __shared__ __align__(16) u64 strigX2[NA][12];   // [x]: (c0,c0)(s0,s0)...(s5,s5)
    __shared__ __align__(16) u64 pairC[NMU][32];    // [nu][lane]: (c[z0],c[z1])
    __shared__ __align__(16) u64 pairS[NMU][32];    // [nu][lane]: (s[z0],s[z1])
    __shared__ __align__(16) u64 sPs[4][36][4];     // per-warp P splats (K-scaled)
    __shared__ __align__(16) float2 sU[4][NMU][NA + 1];  // per-warp U

    for (int i = t; i < DIM; i += 128) sF[i] = feat[b * DIM + i];
    for (int i = t; i < NA * NMU; i += 128) {
        int x = i / NMU, mu = i % NMU;
        float c = g_c[i], s = g_s[i];
        strigX2[x][mu * 2 + 0] = pack2(c, c);
        strigX2[x][mu * 2 + 1] = pack2(s, s);
    }
    // lane-pair trig tables: z0=ln, z1=32+(ln&15)  (192 entries, 128 threads!)
    for (int i = t; i < NMU * 32; i += 128) {
        int nu = i >> 5, ln = i & 31;
        int za = ln, zb = 32 + (ln & 15);
        pairC[nu][ln] = pack2(g_c[za * NMU + nu], g_c[zb * NMU + nu]);
        pairS[nu][ln] = pack2(g_s[za * NMU + nu], g_s[zb * NMU + nu]);
    }
    __syncthreads();

    // K = 2*inv_s*log2(e): fold into P so synthesis output is exp2-ready
    const float K = 2.f / sqrtf(286.f) * 1.4426950408889634f;
    const float* By_g = D + (size_t)y * NA * DIM;   // D[0][y][0][:], L1/L2-hot

    // --- P forms (36 over 32 lanes; lanes 0-3 take a second form) ----------
#pragma unroll
    for (int rep = 0; rep < 2; rep++) {
        int f = lane + rep * 32;
        if (f < 36) {
            int mu = f / 6, nu = f % 6;
            float P00 = 0.f, P01 = 0.f, P10 = 0.f, P11 = 0.f;
            int l0 = mu > nu ? mu : nu;
            for (int l = l0; l <= 5; l++) {
                int dl = 2 * l + 1, off = c_off[l];
                int r0 = l - mu, r1 = l + mu, q0 = l - nu, q1 = l + nu;
                float F00 = sF[off + r0 * dl + q0], F01 = sF[off + r0 * dl + q1];
                float F10 = sF[off + r1 * dl + q0], F11 = sF[off + r1 * dl + q1];
                float B00 = By_g[off + r0 * dl + q0], B01 = By_g[off + r0 * dl + q1];
                float B10 = By_g[off + r1 * dl + q0], B11 = By_g[off + r1 * dl + q1];
                if (mu == 0) { F10 = F11 = 0.f; B10 = B11 = 0.f; }
                if (nu == 0) { F01 = F11 = 0.f; B01 = B11 = 0.f; }
                P00 +=  F00 * B00 + F01 * B01 + F10 * B10 + F11 * B11;
                P01 += -F00 * B01 + F01 * B00 - F10 * B11 + F11 * B10;
                P10 +=  F00 * B10 + F01 * B11 - F10 * B00 - F11 * B01;
                P11 += -F00 * B11 + F01 * B10 + F10 * B01 - F11 * B00;
            }
            sPs[w][f][0] = pack2(P00 * K, P00 * K);
            sPs[w][f][1] = pack2(P01 * K, P01 * K);
            sPs[w][f][2] = pack2(P10 * K, P10 * K);
            sPs[w][f][3] = pack2(P11 * K, P11 * K);
        }
    }
    __syncwarp();

    // --- T stage: packed, broadcast P splats, no in-loop packs --------------
    const int z0 = lane;
    const int z1 = 32 + (lane & 15);
    u64 T0p[6], T1p[6];
#pragma unroll
    for (int mu = 0; mu < 6; mu++) { T0p[mu] = 0ULL; T1p[mu] = 0ULL; }
#pragma unroll
    for (int nu = 0; nu < 6; nu++) {
        u64 cpk = pairC[nu][lane];
        u64 spk = pairS[nu][lane];
#pragma unroll
        for (int mu = 0; mu < 6; mu++) {
            const ulonglong2* Ps = (const ulonglong2*)sPs[w][mu * 6 + nu];
            ulonglong2 Pab = Ps[0];   // (P00,P00),(P01,P01)
            ulonglong2 Pcd = Ps[1];   // (P10,P10),(P11,P11)
            T0p[mu] = fma2(Pab.x, cpk, T0p[mu]);
            T0p[mu] = fma2(Pab.y, spk, T0p[mu]);
            T1p[mu] = fma2(Pcd.x, cpk, T1p[mu]);
            T1p[mu] = fma2(Pcd.y, spk, T1p[mu]);
        }
    }

    // --- fused synthesis + activation + U accumulation (all f32x2) ---------
    const float actq = g_act * qw[y];
    const float m2actq = -2.0f * actq;
    u64 U2[12];
#pragma unroll
    for (int k = 0; k < 12; k++) U2[k] = 0ULL;
#pragma unroll 4
    for (int x = 0; x < NA; x++) {
        const ulonglong2* cp = (const ulonglong2*)strigX2[x];
        ulonglong2 c01 = cp[0], c23 = cp[1], c45 = cp[2];
        ulonglong2 c67 = cp[3], c89 = cp[4], cAB = cp[5];
        // two-tree g accumulation (halves the serial chain)
        u64 gA = 0ULL, gB = 0ULL;
        gA = fma2(c01.x, T0p[0], gA); gA = fma2(c01.y, T1p[0], gA);
        gA = fma2(c23.x, T0p[1], gA); gA = fma2(c23.y, T1p[1], gA);
        gA = fma2(c45.x, T0p[2], gA); gA = fma2(c45.y, T1p[2], gA);
        gB = fma2(c67.x, T0p[3], gB); gB = fma2(c67.y, T1p[3], gB);
        gB = fma2(c89.x, T0p[4], gB); gB = fma2(c89.y, T1p[4], gB);
        gB = fma2(cAB.x, T0p[5], gB); gB = fma2(cAB.y, T1p[5], gB);
        u64 g2 = add2(gA, gB);
        float ga, gb;
        unpack2(g2, ga, gb);
        float ha = fmaf(m2actq, rcpa(ex2a(ga) + 1.0f), actq);
        float hb = fmaf(m2actq, rcpa(ex2a(gb) + 1.0f), actq);
        u64 h2 = pack2(ha, hb);
        U2[0]  = fma2(c01.x, h2, U2[0]);  U2[1]  = fma2(c01.y, h2, U2[1]);
        U2[2]  = fma2(c23.x, h2, U2[2]);  U2[3]  = fma2(c23.y, h2, U2[3]);
        U2[4]  = fma2(c45.x, h2, U2[4]);  U2[5]  = fma2(c45.y, h2, U2[5]);
        U2[6]  = fma2(c67.x, h2, U2[6]);  U2[7]  = fma2(c67.y, h2, U2[7]);
        U2[8]  = fma2(c89.x, h2, U2[8]);  U2[9]  = fma2(c89.y, h2, U2[9]);
        U2[10] = fma2(cAB.x, h2, U2[10]); U2[11] = fma2(cAB.y, h2, U2[11]);
    }
    {
        float U0[12], U1[12];
#pragma unroll
        for (int k = 0; k < 12; k++) unpack2(U2[k], U0[k], U1[k]);
#pragma unroll
        for (int mu = 0; mu < 6; mu++)
            sU[w][mu][z0] = make_float2(U0[2 * mu], U0[2 * mu + 1]);
        if (lane < 16) {
#pragma unroll
            for (int mu = 0; mu < 6; mu++)
                sU[w][mu][z1] = make_float2(U1[2 * mu], U1[2 * mu + 1]);
        }
    }
    __syncwarp();

    // --- Q forms part 1: forms 0..31, one per lane --------------------------
    {
        int mu = lane / 6, nu = lane % 6;
        u64 Qa = 0ULL, Qb = 0ULL;   // (Q00,Q10), (Q01,Q11)
        for (int z = 0; z < NA; z++) {
            u64 u2 = *(const u64*)&sU[w][mu][z];
            ulonglong2 cs = *(const ulonglong2*)&strigX2[z][2 * nu];
            Qa = fma2(u2, cs.x, Qa);
            Qb = fma2(u2, cs.y, Qb);
        }
        float Q00, Q10, Q01, Q11;
        unpack2(Qa, Q00, Q10);
        unpack2(Qb, Q01, Q11);
        *(float4*)(g_Q + ((size_t)(b * NB + y)) * 144 + lane * 4) =
            make_float4(Q00, Q01, Q10, Q11);
    }
    // --- Q forms part 2: forms 32..35 (mu=5, nu=2..5) over 8-lane groups ---
    {
        int grp = lane >> 3;
        int nu = 2 + grp;
        u64 Qa = 0ULL, Qb = 0ULL;
#pragma unroll
        for (int k = 0; k < 6; k++) {
            int z = (lane & 7) * 6 + k;
            u64 u2 = *(const u64*)&sU[w][5][z];
            ulonglong2 cs = *(const ulonglong2*)&strigX2[z][2 * nu];
            Qa = fma2(u2, cs.x, Qa);
            Qb = fma2(u2, cs.y, Qb);
        }
#pragma unroll
        for (int off = 1; off < 8; off <<= 1) {
            Qa = add2(Qa, __shfl_xor_sync(0xffffffffu, Qa, off));
            Qb = add2(Qb, __shfl_xor_sync(0xffffffffu, Qb, off));
        }
        if ((lane & 7) == 0) {
            float Q00, Q10, Q01, Q11;
            unpack2(Qa, Q00, Q10);
            unpack2(Qb, Q01, Q11);
            *(float4*)(g_Q + ((size_t)(b * NB + y)) * 144 + (32 + grp) * 4) =
                make_float4(Q00, Q01, Q10, Q11);
        }
    }
}

// ---------------------------------------------------------------------------
// Scatter (orbit-based): one thread computes ALL 4 outputs of a (mu,nu) orbit
// at level l, sharing the 4 B loads + 1 Q float4 per y across the outputs.
// grid (256 b, 2) x 384 threads = 48 orbit slots x 8 y-lanes (3 y each).
// ---------------------------------------------------------------------------
__global__ __launch_bounds__(384) void scatter_kernel(const float* __restrict__ D,
                                                      float* __restrict__ out) {
    const int b = blockIdx.x;
    const int tid = threadIdx.x;
    int task = blockIdx.y * 48 + (tid >> 3);   // orbit id 0..95
    const int h = tid & 7;                     // y-eighth (3 y each)
    const bool valid = task < 91;
    if (!valid) task = 90;

    int l = 0, rem = task;
    while (rem >= (l + 1) * (l + 1)) { rem -= (l + 1) * (l + 1); l++; }
    int mu = rem / (l + 1), nu = rem % (l + 1);
    int dl = 2 * l + 1, off = c_off[l];
    int r0 = l - mu, r1 = l + mu, q0 = l - nu, q1 = l + nu;
    int i00 = off + r0 * dl + q0, i01 = off + r0 * dl + q1;
    int i10 = off + r1 * dl + q0, i11 = off + r1 * dl + q1;
    int mn4 = (mu * 6 + nu) * 4;

    float o00 = 0.f, o01 = 0.f, o10 = 0.f, o11 = 0.f;
#pragma unroll
    for (int yv = 0; yv < 3; yv++) {
        int y = h * 3 + yv;
        float4 Q = *(const float4*)(g_Q + ((size_t)(b * NB + y)) * 144 + mn4);
        const float* By = D + (size_t)y * NA * DIM;
        float B00 = By[i00], B01 = By[i01], B10 = By[i10], B11 = By[i11];
        o00 += Q.x * B00 - Q.y * B01 + Q.z * B10 - Q.w * B11;
        o01 += Q.x * B01 + Q.y * B00 + Q.z * B11 + Q.w * B10;
        o10 += Q.x * B10 - Q.y * B11 - Q.z * B00 + Q.w * B01;
        o11 += Q.x * B11 + Q.y * B10 - Q.z * B01 - Q.w * B00;
    }
    u64 Pa = pack2(o00, o01), Pb = pack2(o10, o11);
#pragma unroll
    for (int o = 1; o < 8; o <<= 1) {
        Pa = add2(Pa, __shfl_xor_sync(0xffffffffu, Pa, o));
        Pb = add2(Pb, __shfl_xor_sync(0xffffffffu, Pb, o));
    }
    if (valid && h == 0) {
        unpack2(Pa, o00, o01);
        unpack2(Pb, o10, o11);
        const float ss = sqrtf(286.f);
        float* ob = out + (size_t)b * DIM;
        ob[i00] = ss * o00;
        if (nu > 0) ob[i01] = ss * o01;
        if (mu > 0) ob[i10] = ss * o10;
        if (mu > 0 && nu > 0) ob[i11] = ss * o11;
    }
}

extern "C" void kernel_launch(void* const* d_in, const int* in_sizes, int n_in,
                              void* d_out, int out_size) {
    const float* feat = (const float*)d_in[0];  // [256, 286]
    const float* D    = (const float*)d_in[1];  // [48, 24, 48, 286]
    const float* qw   = (const float*)d_in[2];  // [24]
    float* out        = (float*)d_out;          // [256, 286]

    prep_kernel<<<1, 512>>>(D);
    so3_main<<<dim3(NBATCH, 6), 128>>>(feat, D, qw);
    scatter_kernel<<<dim3(NBATCH, 2), 384>>>(D, out);
}

// round 15
// speedup vs baseline: 1.0067x; 1.0067x over previous
#include <cuda_runtime.h>
#include <math.h>

#define NA 48
#define NB 24
#define DIM 286
#define NBATCH 256
#define NMU 6
#define L5OFF 165

typedef unsigned long long u64;

// f32x2 packed helpers (FFMA2 — PTX-only on sm_103a)
__device__ __forceinline__ u64 pack2(float lo, float hi) {
    u64 r; asm("mov.b64 %0, {%1, %2};" : "=l"(r) : "f"(lo), "f"(hi)); return r;
}
__device__ __forceinline__ void unpack2(u64 v, float& lo, float& hi) {
    asm("mov.b64 {%0, %1}, %2;" : "=f"(lo), "=f"(hi) : "l"(v));
}
__device__ __forceinline__ u64 fma2(u64 a, u64 b, u64 c) {
    u64 r; asm("fma.rn.f32x2 %0, %1, %2, %3;" : "=l"(r) : "l"(a), "l"(b), "l"(c)); return r;
}
__device__ __forceinline__ u64 add2(u64 a, u64 b) {
    u64 r; asm("add.rn.f32x2 %0, %1, %2;" : "=l"(r) : "l"(a), "l"(b)); return r;
}
__device__ __forceinline__ float ex2a(float x) {
    float r; asm("ex2.approx.f32 %0, %1;" : "=f"(r) : "f"(x)); return r;
}
__device__ __forceinline__ float rcpa(float x) {
    float r; asm("rcp.approx.f32 %0, %1;" : "=f"(r) : "f"(x)); return r;
}

// Scratch (static device globals; no allocation)
__device__ float g_c[NA * NMU];                // cos-like per (x, mu)
__device__ float g_s[NA * NMU];                // sin-like per (x, mu)
__device__ float g_act;                        // normalize2mom constant for tanh
__device__ float g_part[48];                   // partials for activation integral
__device__ float g_Q[NBATCH * NB * 144];       // Q forms [b][y][mn*4+c]

__constant__ int c_off[6] = {0, 1, 10, 35, 84, 165};

// ---------------------------------------------------------------------------
// ACT_CST integral partials: trapz of tanh(x)^2*N(0,1), 20001 pts, 48 CTAs.
// (quadrature error ~3e-6 rel vs reference's 1e6-pt trapz — invisible)
// ---------------------------------------------------------------------------
__global__ void act_kernel() {
    const float L2E2 = 2.8853900817779268f;  // 2*log2(e)
    int tid = blockIdx.x * blockDim.x + threadIdx.x;  // 48*256 = 12288
    float sum = 0.f;
    for (int i = tid; i <= 20000; i += 12288) {
        float x = -12.f + (float)i * 1.2e-3f;
        float th = 1.0f - 2.0f * rcpa(ex2a(x * L2E2) + 1.0f);
        sum += th * th * __expf(-0.5f * x * x);
    }
    for (int o = 16; o; o >>= 1) sum += __shfl_down_sync(0xffffffffu, sum, o);
    __shared__ float ws[8];
    int w = threadIdx.x >> 5;
    if ((threadIdx.x & 31) == 0) ws[w] = sum;
    __syncthreads();
    if (threadIdx.x == 0) {
        float b = 0.f;
        for (int i = 0; i < 8; i++) b += ws[i];
        g_part[blockIdx.x] = b;
    }
}

// ---------------------------------------------------------------------------
// Prep: trig extraction (Ra5[x] = D5[x,0,0]*D5[0,0,0]^T/11) + act reduce.
// ---------------------------------------------------------------------------
__global__ void prep_kernel(const float* __restrict__ D) {
    int t = threadIdx.x;
    if (t < NA * NMU) {
        int x = t / NMU, mu = t % NMU;
        int p0 = 5 - mu, p1 = 5 + mu;
        const float* X = D + (size_t)x * NB * NA * DIM + L5OFF;
        const float* Z = D + L5OFF;
        float a00 = 0.f, a01 = 0.f, a10 = 0.f, a11 = 0.f;
        for (int k = 0; k < 11; k++) {
            float xp0 = X[p0 * 11 + k], xp1 = X[p1 * 11 + k];
            float zp0 = Z[p0 * 11 + k], zp1 = Z[p1 * 11 + k];
            a00 += xp0 * zp0; a01 += xp0 * zp1;
            a10 += xp1 * zp0; a11 += xp1 * zp1;
        }
        const float inv11 = 1.f / 11.f;
        g_c[t] = 0.5f * (a00 + a11) * inv11;
        g_s[t] = 0.5f * (a01 - a10) * inv11;
    }
    if (t == 0) {
        float tot = 0.f;
        for (int i = 0; i < 48; i++) tot += g_part[i];
        float I = tot * 1.2e-3f * 0.3989422804014327f;
        g_act = 1.0f / sqrtf(I);
    }
}

// ---------------------------------------------------------------------------
// Main (warp-autonomous, f32x2): grid (b, ys) x 128 threads. Warp w handles
// y = ys*4 + w. P (K-prescaled, stored as pre-splatted u64 pairs) ->
// T (broadcast LDS, no packs) -> fused synth+tanh+U -> Q.
// Lane owns z0=lane, z1=32+(lane&15).
// ---------------------------------------------------------------------------
__global__ __launch_bounds__(128) void so3_main(const float* __restrict__ feat,
                                                const float* __restrict__ D,
                                                const float* __restrict__ qw) {
    const int b = blockIdx.x;
    const int t = threadIdx.x;
    const int w = t >> 5;
    const int lane = t & 31;
    const int y = blockIdx.y * 4 + w;

    __shared__ float sF[DIM];
    __shared__ __align__(16) u64 strigX2[NA][12];   // [x]: (c0,c0)(s0,s0)...(s5,s5)
    __shared__ __align__(16) u64 pairC[NMU][32];    // [nu][lane]: (c[z0],c[z1])
    __shared__ __align__(16) u64 pairS[NMU][32];    // [nu][lane]: (s[z0],s[z1])
    __shared__ __align__(16) u64 sPs[4][36][4];     // per-warp P splats (K-scaled)
    __shared__ __align__(16) float2 sU[4][NMU][NA + 1];  // per-warp U

    for (int i = t; i < DIM; i += 128) sF[i] = feat[b * DIM + i];
    for (int i = t; i < NA * NMU; i += 128) {
        int x = i / NMU, mu = i % NMU;
        float c = g_c[i], s = g_s[i];
        strigX2[x][mu * 2 + 0] = pack2(c, c);
        strigX2[x][mu * 2 + 1] = pack2(s, s);
    }
    // lane-pair trig tables: z0=ln, z1=32+(ln&15)  (192 entries, 128 threads)
    for (int i = t; i < NMU * 32; i += 128) {
        int nu = i >> 5, ln = i & 31;
        int za = ln, zb = 32 + (ln & 15);
        pairC[nu][ln] = pack2(g_c[za * NMU + nu], g_c[zb * NMU + nu]);
        pairS[nu][ln] = pack2(g_s[za * NMU + nu], g_s[zb * NMU + nu]);
    }
    __syncthreads();

    // K = 2*inv_s*log2(e): fold into P so synthesis output is exp2-ready
    const float K = 2.f / sqrtf(286.f) * 1.4426950408889634f;
    const float* By_g = D + (size_t)y * NA * DIM;   // D[0][y][0][:], L1/L2-hot

    // --- P forms (36 over 32 lanes; lanes 0-3 take a second form) ----------
#pragma unroll
    for (int rep = 0; rep < 2; rep++) {
        int f = lane + rep * 32;
        if (f < 36) {
            int mu = f / 6, nu = f % 6;
            float P00 = 0.f, P01 = 0.f, P10 = 0.f, P11 = 0.f;
            int l0 = mu > nu ? mu : nu;
            for (int l = l0; l <= 5; l++) {
                int dl = 2 * l + 1, off = c_off[l];
                int r0 = l - mu, r1 = l + mu, q0 = l - nu, q1 = l + nu;
                float F00 = sF[off + r0 * dl + q0], F01 = sF[off + r0 * dl + q1];
                float F10 = sF[off + r1 * dl + q0], F11 = sF[off + r1 * dl + q1];
                float B00 = By_g[off + r0 * dl + q0], B01 = By_g[off + r0 * dl + q1];
                float B10 = By_g[off + r1 * dl + q0], B11 = By_g[off + r1 * dl + q1];
                if (mu == 0) { F10 = F11 = 0.f; B10 = B11 = 0.f; }
                if (nu == 0) { F01 = F11 = 0.f; B01 = B11 = 0.f; }
                P00 +=  F00 * B00 + F01 * B01 + F10 * B10 + F11 * B11;
                P01 += -F00 * B01 + F01 * B00 - F10 * B11 + F11 * B10;
                P10 +=  F00 * B10 + F01 * B11 - F10 * B00 - F11 * B01;
                P11 += -F00 * B11 + F01 * B10 + F10 * B01 - F11 * B00;
            }
            sPs[w][f][0] = pack2(P00 * K, P00 * K);
            sPs[w][f][1] = pack2(P01 * K, P01 * K);
            sPs[w][f][2] = pack2(P10 * K, P10 * K);
            sPs[w][f][3] = pack2(P11 * K, P11 * K);
        }
    }
    __syncwarp();

    // --- T stage: packed, broadcast P splats, no in-loop packs --------------
    const int z0 = lane;
    const int z1 = 32 + (lane & 15);
    u64 T0p[6], T1p[6];
#pragma unroll
    for (int mu = 0; mu < 6; mu++) { T0p[mu] = 0ULL; T1p[mu] = 0ULL; }
#pragma unroll
    for (int nu = 0; nu < 6; nu++) {
        u64 cpk = pairC[nu][lane];
        u64 spk = pairS[nu][lane];
#pragma unroll
        for (int mu = 0; mu < 6; mu++) {
            const ulonglong2* Ps = (const ulonglong2*)sPs[w][mu * 6 + nu];
            ulonglong2 Pab = Ps[0];   // (P00,P00),(P01,P01)
            ulonglong2 Pcd = Ps[1];   // (P10,P10),(P11,P11)
            T0p[mu] = fma2(Pab.x, cpk, T0p[mu]);
            T0p[mu] = fma2(Pab.y, spk, T0p[mu]);
            T1p[mu] = fma2(Pcd.x, cpk, T1p[mu]);
            T1p[mu] = fma2(Pcd.y, spk, T1p[mu]);
        }
    }

    // --- fused synthesis + activation + U accumulation (all f32x2) ---------
    const float actq = g_act * qw[y];
    const float m2actq = -2.0f * actq;
    u64 U2[12];
#pragma unroll
    for (int k = 0; k < 12; k++) U2[k] = 0ULL;
#pragma unroll 4
    for (int x = 0; x < NA; x++) {
        const ulonglong2* cp = (const ulonglong2*)strigX2[x];
        ulonglong2 c01 = cp[0], c23 = cp[1], c45 = cp[2];
        ulonglong2 c67 = cp[3], c89 = cp[4], cAB = cp[5];
        // two-tree g accumulation (halves the serial chain)
        u64 gA = 0ULL, gB = 0ULL;
        gA = fma2(c01.x, T0p[0], gA); gA = fma2(c01.y, T1p[0], gA);
        gA = fma2(c23.x, T0p[1], gA); gA = fma2(c23.y, T1p[1], gA);
        gA = fma2(c45.x, T0p[2], gA); gA = fma2(c45.y, T1p[2], gA);
        gB = fma2(c67.x, T0p[3], gB); gB = fma2(c67.y, T1p[3], gB);
        gB = fma2(c89.x, T0p[4], gB); gB = fma2(c89.y, T1p[4], gB);
        gB = fma2(cAB.x, T0p[5], gB); gB = fma2(cAB.y, T1p[5], gB);
        u64 g2 = add2(gA, gB);
        float ga, gb;
        unpack2(g2, ga, gb);
        float ha = fmaf(m2actq, rcpa(ex2a(ga) + 1.0f), actq);
        float hb = fmaf(m2actq, rcpa(ex2a(gb) + 1.0f), actq);
        u64 h2 = pack2(ha, hb);
        U2[0]  = fma2(c01.x, h2, U2[0]);  U2[1]  = fma2(c01.y, h2, U2[1]);
        U2[2]  = fma2(c23.x, h2, U2[2]);  U2[3]  = fma2(c23.y, h2, U2[3]);
        U2[4]  = fma2(c45.x, h2, U2[4]);  U2[5]  = fma2(c45.y, h2, U2[5]);
        U2[6]  = fma2(c67.x, h2, U2[6]);  U2[7]  = fma2(c67.y, h2, U2[7]);
        U2[8]  = fma2(c89.x, h2, U2[8]);  U2[9]  = fma2(c89.y, h2, U2[9]);
        U2[10] = fma2(cAB.x, h2, U2[10]); U2[11] = fma2(cAB.y, h2, U2[11]);
    }
    {
        float U0[12], U1[12];
#pragma unroll
        for (int k = 0; k < 12; k++) unpack2(U2[k], U0[k], U1[k]);
#pragma unroll
        for (int mu = 0; mu < 6; mu++)
            sU[w][mu][z0] = make_float2(U0[2 * mu], U0[2 * mu + 1]);
        if (lane < 16) {
#pragma unroll
            for (int mu = 0; mu < 6; mu++)
                sU[w][mu][z1] = make_float2(U1[2 * mu], U1[2 * mu + 1]);
        }
    }
    __syncwarp();

    // --- Q forms part 1: forms 0..31, one per lane --------------------------
    {
        int mu = lane / 6, nu = lane % 6;
        u64 Qa = 0ULL, Qb = 0ULL;   // (Q00,Q10), (Q01,Q11)
        for (int z = 0; z < NA; z++) {
            u64 u2 = *(const u64*)&sU[w][mu][z];
            ulonglong2 cs = *(const ulonglong2*)&strigX2[z][2 * nu];
            Qa = fma2(u2, cs.x, Qa);
            Qb = fma2(u2, cs.y, Qb);
        }
        float Q00, Q10, Q01, Q11;
        unpack2(Qa, Q00, Q10);
        unpack2(Qb, Q01, Q11);
        *(float4*)(g_Q + ((size_t)(b * NB + y)) * 144 + lane * 4) =
            make_float4(Q00, Q01, Q10, Q11);
    }
    // --- Q forms part 2: forms 32..35 (mu=5, nu=2..5) over 8-lane groups ---
    {
        int grp = lane >> 3;
        int nu = 2 + grp;
        u64 Qa = 0ULL, Qb = 0ULL;
#pragma unroll
        for (int k = 0; k < 6; k++) {
            int z = (lane & 7) * 6 + k;
            u64 u2 = *(const u64*)&sU[w][5][z];
            ulonglong2 cs = *(const ulonglong2*)&strigX2[z][2 * nu];
            Qa = fma2(u2, cs.x, Qa);
            Qb = fma2(u2, cs.y, Qb);
        }
#pragma unroll
        for (int off = 1; off < 8; off <<= 1) {
            Qa = add2(Qa, __shfl_xor_sync(0xffffffffu, Qa, off));
            Qb = add2(Qb, __shfl_xor_sync(0xffffffffu, Qb, off));
        }
        if ((lane & 7) == 0) {
            float Q00, Q10, Q01, Q11;
            unpack2(Qa, Q00, Q10);
            unpack2(Qb, Q01, Q11);
            *(float4*)(g_Q + ((size_t)(b * NB + y)) * 144 + (32 + grp) * 4) =
                make_float4(Q00, Q01, Q10, Q11);
        }
    }
}

// ---------------------------------------------------------------------------
// Scatter (orbit-based): one thread computes ALL 4 outputs of a (mu,nu) orbit
// at level l, sharing the 4 B loads + 1 Q float4 per y across the outputs.
// grid (256 b, 2) x 384 threads = 48 orbit slots x 8 y-lanes (3 y each).
// ---------------------------------------------------------------------------
__global__ __launch_bounds__(384) void scatter_kernel(const float* __restrict__ D,
                                                      float* __restrict__ out) {
    const int b = blockIdx.x;
    const int tid = threadIdx.x;
    int task = blockIdx.y * 48 + (tid >> 3);   // orbit id 0..95
    const int h = tid & 7;                     // y-eighth (3 y each)
    const bool valid = task < 91;
    if (!valid) task = 90;

    int l = 0, rem = task;
    while (rem >= (l + 1) * (l + 1)) { rem -= (l + 1) * (l + 1); l++; }
    int mu = rem / (l + 1), nu = rem % (l + 1);
    int dl = 2 * l + 1, off = c_off[l];
    int r0 = l - mu, r1 = l + mu, q0 = l - nu, q1 = l + nu;
    int i00 = off + r0 * dl + q0, i01 = off + r0 * dl + q1;
    int i10 = off + r1 * dl + q0, i11 = off + r1 * dl + q1;
    int mn4 = (mu * 6 + nu) * 4;

    float o00 = 0.f, o01 = 0.f, o10 = 0.f, o11 = 0.f;
#pragma unroll
    for (int yv = 0; yv < 3; yv++) {
        int y = h * 3 + yv;
        float4 Q = *(const float4*)(g_Q + ((size_t)(b * NB + y)) * 144 + mn4);
        const float* By = D + (size_t)y * NA * DIM;
        float B00 = By[i00], B01 = By[i01], B10 = By[i10], B11 = By[i11];
        o00 += Q.x * B00 - Q.y * B01 + Q.z * B10 - Q.w * B11;
        o01 += Q.x * B01 + Q.y * B00 + Q.z * B11 + Q.w * B10;
        o10 += Q.x * B10 - Q.y * B11 - Q.z * B00 + Q.w * B01;
        o11 += Q.x * B11 + Q.y * B10 - Q.z * B01 - Q.w * B00;
    }
    u64 Pa = pack2(o00, o01), Pb = pack2(o10, o11);
#pragma unroll
    for (int o = 1; o < 8; o <<= 1) {
        Pa = add2(Pa, __shfl_xor_sync(0xffffffffu, Pa, o));
        Pb = add2(Pb, __shfl_xor_sync(0xffffffffu, Pb, o));
    }
    if (valid && h == 0) {
        unpack2(Pa, o00, o01);
        unpack2(Pb, o10, o11);
        const float ss = sqrtf(286.f);
        float* ob = out + (size_t)b * DIM;
        ob[i00] = ss * o00;
        if (nu > 0) ob[i01] = ss * o01;
        if (mu > 0) ob[i10] = ss * o10;
        if (mu > 0 && nu > 0) ob[i11] = ss * o11;
    }
}

extern "C" void kernel_launch(void* const* d_in, const int* in_sizes, int n_in,
                              void* d_out, int out_size) {
    const float* feat = (const float*)d_in[0];  // [256, 286]
    const float* D    = (const float*)d_in[1];  // [48, 24, 48, 286]
    const float* qw   = (const float*)d_in[2];  // [24]
    float* out        = (float*)d_out;          // [256, 286]

    act_kernel<<<48, 256>>>();
    prep_kernel<<<1, 512>>>(D);
    so3_main<<<dim3(NBATCH, 6), 128>>>(feat, D, qw);
    scatter_kernel<<<dim3(NBATCH, 2), 384>>>(D, out);
}

// round 16
// speedup vs baseline: 1.0355x; 1.0287x over previous
#include <cuda_runtime.h>
#include <math.h>

#define NA 48
#define NB 24
#define DIM 286
#define NBATCH 256
#define NMU 6
#define L5OFF 165

typedef unsigned long long u64;

// f32x2 packed helpers (FFMA2 — PTX-only on sm_103a)
__device__ __forceinline__ u64 pack2(float lo, float hi) {
    u64 r; asm("mov.b64 %0, {%1, %2};" : "=l"(r) : "f"(lo), "f"(hi)); return r;
}
__device__ __forceinline__ void unpack2(u64 v, float& lo, float& hi) {
    asm("mov.b64 {%0, %1}, %2;" : "=f"(lo), "=f"(hi) : "l"(v));
}
__device__ __forceinline__ u64 fma2(u64 a, u64 b, u64 c) {
    u64 r; asm("fma.rn.f32x2 %0, %1, %2, %3;" : "=l"(r) : "l"(a), "l"(b), "l"(c)); return r;
}
__device__ __forceinline__ u64 add2(u64 a, u64 b) {
    u64 r; asm("add.rn.f32x2 %0, %1, %2;" : "=l"(r) : "l"(a), "l"(b)); return r;
}
__device__ __forceinline__ float ex2a(float x) {
    float r; asm("ex2.approx.f32 %0, %1;" : "=f"(r) : "f"(x)); return r;
}
__device__ __forceinline__ float rcpa(float x) {
    float r; asm("rcp.approx.f32 %0, %1;" : "=f"(r) : "f"(x)); return r;
}

// Scratch (static device globals; no allocation)
__device__ float g_c[NA * NMU];                // cos-like per (x, mu)
__device__ float g_s[NA * NMU];                // sin-like per (x, mu)
__device__ float g_act;                        // normalize2mom constant for tanh
__device__ float g_part[48];                   // partials for activation integral
__device__ float g_Q[NBATCH * NB * 144];       // Q forms [b][y][mn*4+c]

__constant__ int c_off[6] = {0, 1, 10, 35, 84, 165};

// ---------------------------------------------------------------------------
// ACT_CST integral partials: trapz of tanh(x)^2*N(0,1), 20001 pts, 48 CTAs.
// ---------------------------------------------------------------------------
__global__ void act_kernel() {
    const float L2E2 = 2.8853900817779268f;  // 2*log2(e)
    int tid = blockIdx.x * blockDim.x + threadIdx.x;  // 48*256 = 12288
    float sum = 0.f;
    for (int i = tid; i <= 20000; i += 12288) {
        float x = -12.f + (float)i * 1.2e-3f;
        float th = 1.0f - 2.0f * rcpa(ex2a(x * L2E2) + 1.0f);
        sum += th * th * __expf(-0.5f * x * x);
    }
    for (int o = 16; o; o >>= 1) sum += __shfl_down_sync(0xffffffffu, sum, o);
    __shared__ float ws[8];
    int w = threadIdx.x >> 5;
    if ((threadIdx.x & 31) == 0) ws[w] = sum;
    __syncthreads();
    if (threadIdx.x == 0) {
        float b = 0.f;
        for (int i = 0; i < 8; i++) b += ws[i];
        g_part[blockIdx.x] = b;
    }
}

// ---------------------------------------------------------------------------
// Prep: trig extraction (Ra5[x] = D5[x,0,0]*D5[0,0,0]^T/11) + act reduce.
// ---------------------------------------------------------------------------
__global__ void prep_kernel(const float* __restrict__ D) {
    int t = threadIdx.x;
    if (t < NA * NMU) {
        int x = t / NMU, mu = t % NMU;
        int p0 = 5 - mu, p1 = 5 + mu;
        const float* X = D + (size_t)x * NB * NA * DIM + L5OFF;
        const float* Z = D + L5OFF;
        float a00 = 0.f, a01 = 0.f, a10 = 0.f, a11 = 0.f;
        for (int k = 0; k < 11; k++) {
            float xp0 = X[p0 * 11 + k], xp1 = X[p1 * 11 + k];
            float zp0 = Z[p0 * 11 + k], zp1 = Z[p1 * 11 + k];
            a00 += xp0 * zp0; a01 += xp0 * zp1;
            a10 += xp1 * zp0; a11 += xp1 * zp1;
        }
        const float inv11 = 1.f / 11.f;
        g_c[t] = 0.5f * (a00 + a11) * inv11;
        g_s[t] = 0.5f * (a01 - a10) * inv11;
    }
    if (t == 0) {
        float tot = 0.f;
        for (int i = 0; i < 48; i++) tot += g_part[i];
        float I = tot * 1.2e-3f * 0.3989422804014327f;
        g_act = 1.0f / sqrtf(I);
    }
}

// ---------------------------------------------------------------------------
// Main (warp-autonomous, f32x2) — the 55.8us-verified round-12 structure:
// scalar T compute + in-register K-prescaled packs (ALU-pipe MOVs dual-issue
// with FFMA2), float4 sP4, ex2/rcp tanh. Only delta: two-tree g2.
// ---------------------------------------------------------------------------
__global__ __launch_bounds__(128) void so3_main(const float* __restrict__ feat,
                                                const float* __restrict__ D,
                                                const float* __restrict__ qw) {
    const int b = blockIdx.x;
    const int t = threadIdx.x;
    const int w = t >> 5;
    const int lane = t & 31;
    const int y = blockIdx.y * 4 + w;

    __shared__ float sF[DIM];
    __shared__ __align__(16) u64 strigX2[NA][12];   // [x]: (c0,c0)(s0,s0)...(s5,s5)
    __shared__ float2 strigT[NMU][NA + 1];          // [mu][z], padded row
    __shared__ float4 sP4[4][36];                   // per-warp P forms (K-prescaled)
    __shared__ __align__(16) float2 sU[4][NMU][NA + 1];  // per-warp U

    for (int i = t; i < DIM; i += 128) sF[i] = feat[b * DIM + i];
    for (int i = t; i < NA * NMU; i += 128) {
        int x = i / NMU, mu = i % NMU;
        float c = g_c[i], s = g_s[i];
        strigX2[x][mu * 2 + 0] = pack2(c, c);
        strigX2[x][mu * 2 + 1] = pack2(s, s);
        strigT[mu][x] = make_float2(c, s);
    }
    __syncthreads();

    // K = 2*inv_s*log2(e): fold into P so synthesis output is exp2-ready
    const float K = 2.f / sqrtf(286.f) * 1.4426950408889634f;
    const float* By_g = D + (size_t)y * NA * DIM;   // D[0][y][0][:], L1/L2-hot

    // --- P forms (36 over 32 lanes; lanes 0-3 take a second form) ----------
#pragma unroll
    for (int rep = 0; rep < 2; rep++) {
        int f = lane + rep * 32;
        if (f < 36) {
            int mu = f / 6, nu = f % 6;
            float P00 = 0.f, P01 = 0.f, P10 = 0.f, P11 = 0.f;
            int l0 = mu > nu ? mu : nu;
            for (int l = l0; l <= 5; l++) {
                int dl = 2 * l + 1, off = c_off[l];
                int r0 = l - mu, r1 = l + mu, q0 = l - nu, q1 = l + nu;
                float F00 = sF[off + r0 * dl + q0], F01 = sF[off + r0 * dl + q1];
                float F10 = sF[off + r1 * dl + q0], F11 = sF[off + r1 * dl + q1];
                float B00 = By_g[off + r0 * dl + q0], B01 = By_g[off + r0 * dl + q1];
                float B10 = By_g[off + r1 * dl + q0], B11 = By_g[off + r1 * dl + q1];
                if (mu == 0) { F10 = F11 = 0.f; B10 = B11 = 0.f; }
                if (nu == 0) { F01 = F11 = 0.f; B01 = B11 = 0.f; }
                P00 +=  F00 * B00 + F01 * B01 + F10 * B10 + F11 * B11;
                P01 += -F00 * B01 + F01 * B00 - F10 * B11 + F11 * B10;
                P10 +=  F00 * B10 + F01 * B11 - F10 * B00 - F11 * B01;
                P11 += -F00 * B11 + F01 * B10 + F10 * B01 - F11 * B00;
            }
            sP4[w][f] = make_float4(P00 * K, P01 * K, P10 * K, P11 * K);
        }
    }
    __syncwarp();

    // --- T stage (packed f32x2: (z0,z1) lanes; in-register packs) ----------
    const int z0 = lane;
    const int z1 = 32 + (lane & 15);
    u64 T0p[6], T1p[6];
#pragma unroll
    for (int mu = 0; mu < 6; mu++) { T0p[mu] = 0ULL; T1p[mu] = 0ULL; }
#pragma unroll
    for (int nu = 0; nu < 6; nu++) {
        float2 ca = strigT[nu][z0];
        float2 cb = strigT[nu][z1];
        u64 cpk = pack2(ca.x, cb.x);
        u64 spk = pack2(ca.y, cb.y);
#pragma unroll
        for (int mu = 0; mu < 6; mu++) {
            float4 P = sP4[w][mu * 6 + nu];
            T0p[mu] = fma2(pack2(P.x, P.x), cpk, T0p[mu]);
            T0p[mu] = fma2(pack2(P.y, P.y), spk, T0p[mu]);
            T1p[mu] = fma2(pack2(P.z, P.z), cpk, T1p[mu]);
            T1p[mu] = fma2(pack2(P.w, P.w), spk, T1p[mu]);
        }
    }

    // --- fused synthesis + activation + U accumulation (all f32x2) ---------
    const float actq = g_act * qw[y];
    const float m2actq = -2.0f * actq;
    u64 U2[12];
#pragma unroll
    for (int k = 0; k < 12; k++) U2[k] = 0ULL;
#pragma unroll 4
    for (int x = 0; x < NA; x++) {
        const ulonglong2* cp = (const ulonglong2*)strigX2[x];
        ulonglong2 c01 = cp[0], c23 = cp[1], c45 = cp[2];
        ulonglong2 c67 = cp[3], c89 = cp[4], cAB = cp[5];
        // two-tree g accumulation (halves the serial FFMA2 chain)
        u64 gA = 0ULL, gB = 0ULL;
        gA = fma2(c01.x, T0p[0], gA); gA = fma2(c01.y, T1p[0], gA);
        gA = fma2(c23.x, T0p[1], gA); gA = fma2(c23.y, T1p[1], gA);
        gA = fma2(c45.x, T0p[2], gA); gA = fma2(c45.y, T1p[2], gA);
        gB = fma2(c67.x, T0p[3], gB); gB = fma2(c67.y, T1p[3], gB);
        gB = fma2(c89.x, T0p[4], gB); gB = fma2(c89.y, T1p[4], gB);
        gB = fma2(cAB.x, T0p[5], gB); gB = fma2(cAB.y, T1p[5], gB);
        u64 g2 = add2(gA, gB);
        float ga, gb;
        unpack2(g2, ga, gb);
        float ha = fmaf(m2actq, rcpa(ex2a(ga) + 1.0f), actq);
        float hb = fmaf(m2actq, rcpa(ex2a(gb) + 1.0f), actq);
        u64 h2 = pack2(ha, hb);
        U2[0]  = fma2(c01.x, h2, U2[0]);  U2[1]  = fma2(c01.y, h2, U2[1]);
        U2[2]  = fma2(c23.x, h2, U2[2]);  U2[3]  = fma2(c23.y, h2, U2[3]);
        U2[4]  = fma2(c45.x, h2, U2[4]);  U2[5]  = fma2(c45.y, h2, U2[5]);
        U2[6]  = fma2(c67.x, h2, U2[6]);  U2[7]  = fma2(c67.y, h2, U2[7]);
        U2[8]  = fma2(c89.x, h2, U2[8]);  U2[9]  = fma2(c89.y, h2, U2[9]);
        U2[10] = fma2(cAB.x, h2, U2[10]); U2[11] = fma2(cAB.y, h2, U2[11]);
    }
    {
        float U0[12], U1[12];
#pragma unroll
        for (int k = 0; k < 12; k++) unpack2(U2[k], U0[k], U1[k]);
#pragma unroll
        for (int mu = 0; mu < 6; mu++)
            sU[w][mu][z0] = make_float2(U0[2 * mu], U0[2 * mu + 1]);
        if (lane < 16) {
#pragma unroll
            for (int mu = 0; mu < 6; mu++)
                sU[w][mu][z1] = make_float2(U1[2 * mu], U1[2 * mu + 1]);
        }
    }
    __syncwarp();

    // --- Q forms part 1: forms 0..31, one per lane --------------------------
    {
        int mu = lane / 6, nu = lane % 6;
        u64 Qa = 0ULL, Qb = 0ULL;   // (Q00,Q10), (Q01,Q11)
        for (int z = 0; z < NA; z++) {
            u64 u2 = *(const u64*)&sU[w][mu][z];
            ulonglong2 cs = *(const ulonglong2*)&strigX2[z][2 * nu];
            Qa = fma2(u2, cs.x, Qa);
            Qb = fma2(u2, cs.y, Qb);
        }
        float Q00, Q10, Q01, Q11;
        unpack2(Qa, Q00, Q10);
        unpack2(Qb, Q01, Q11);
        *(float4*)(g_Q + ((size_t)(b * NB + y)) * 144 + lane * 4) =
            make_float4(Q00, Q01, Q10, Q11);
    }
    // --- Q forms part 2: forms 32..35 (mu=5, nu=2..5) over 8-lane groups ---
    {
        int grp = lane >> 3;
        int nu = 2 + grp;
        u64 Qa = 0ULL, Qb = 0ULL;
#pragma unroll
        for (int k = 0; k < 6; k++) {
            int z = (lane & 7) * 6 + k;
            u64 u2 = *(const u64*)&sU[w][5][z];
            ulonglong2 cs = *(const ulonglong2*)&strigX2[z][2 * nu];
            Qa = fma2(u2, cs.x, Qa);
            Qb = fma2(u2, cs.y, Qb);
        }
#pragma unroll
        for (int off = 1; off < 8; off <<= 1) {
            Qa = add2(Qa, __shfl_xor_sync(0xffffffffu, Qa, off));
            Qb = add2(Qb, __shfl_xor_sync(0xffffffffu, Qb, off));
        }
        if ((lane & 7) == 0) {
            float Q00, Q10, Q01, Q11;
            unpack2(Qa, Q00, Q10);
            unpack2(Qb, Q01, Q11);
            *(float4*)(g_Q + ((size_t)(b * NB + y)) * 144 + (32 + grp) * 4) =
                make_float4(Q00, Q01, Q10, Q11);
        }
    }
}

// ---------------------------------------------------------------------------
// Scatter (orbit-based): one thread computes ALL 4 outputs of a (mu,nu) orbit
// at level l, sharing the 4 B loads + 1 Q float4 per y across the outputs.
// grid (256 b, 2) x 384 threads = 48 orbit slots x 8 y-lanes (3 y each).
// ---------------------------------------------------------------------------
__global__ __launch_bounds__(384) void scatter_kernel(const float* __restrict__ D,
                                                      float* __restrict__ out) {
    const int b = blockIdx.x;
    const int tid = threadIdx.x;
    int task = blockIdx.y * 48 + (tid >> 3);   // orbit id 0..95
    const int h = tid & 7;                     // y-eighth (3 y each)
    const bool valid = task < 91;
    if (!valid) task = 90;

    int l = 0, rem = task;
    while (rem >= (l + 1) * (l + 1)) { rem -= (l + 1) * (l + 1); l++; }
    int mu = rem / (l + 1), nu = rem % (l + 1);
    int dl = 2 * l + 1, off = c_off[l];
    int r0 = l - mu, r1 = l + mu, q0 = l - nu, q1 = l + nu;
    int i00 = off + r0 * dl + q0, i01 = off + r0 * dl + q1;
    int i10 = off + r1 * dl + q0, i11 = off + r1 * dl + q1;
    int mn4 = (mu * 6 + nu) * 4;

    float o00 = 0.f, o01 = 0.f, o10 = 0.f, o11 = 0.f;
#pragma unroll
    for (int yv = 0; yv < 3; yv++) {
        int y = h * 3 + yv;
        float4 Q = *(const float4*)(g_Q + ((size_t)(b * NB + y)) * 144 + mn4);
        const float* By = D + (size_t)y * NA * DIM;
        float B00 = By[i00], B01 = By[i01], B10 = By[i10], B11 = By[i11];
        o00 += Q.x * B00 - Q.y * B01 + Q.z * B10 - Q.w * B11;
        o01 += Q.x * B01 + Q.y * B00 + Q.z * B11 + Q.w * B10;
        o10 += Q.x * B10 - Q.y * B11 - Q.z * B00 + Q.w * B01;
        o11 += Q.x * B11 + Q.y * B10 - Q.z * B01 - Q.w * B00;
    }
    u64 Pa = pack2(o00, o01), Pb = pack2(o10, o11);
#pragma unroll
    for (int o = 1; o < 8; o <<= 1) {
        Pa = add2(Pa, __shfl_xor_sync(0xffffffffu, Pa, o));
        Pb = add2(Pb, __shfl_xor_sync(0xffffffffu, Pb, o));
    }
    if (valid && h == 0) {
        unpack2(Pa, o00, o01);
        unpack2(Pb, o10, o11);
        const float ss = sqrtf(286.f);
        float* ob = out + (size_t)b * DIM;
        ob[i00] = ss * o00;
        if (nu > 0) ob[i01] = ss * o01;
        if (mu > 0) ob[i10] = ss * o10;
        if (mu > 0 && nu > 0) ob[i11] = ss * o11;
    }
}

extern "C" void kernel_launch(void* const* d_in, const int* in_sizes, int n_in,
                              void* d_out, int out_size) {
    const float* feat = (const float*)d_in[0];  // [256, 286]
    const float* D    = (const float*)d_in[1];  // [48, 24, 48, 286]
    const float* qw   = (const float*)d_in[2];  // [24]
    float* out        = (float*)d_out;          // [256, 286]

    act_kernel<<<48, 256>>>();
    prep_kernel<<<1, 512>>>(D);
    so3_main<<<dim3(NBATCH, 6), 128>>>(feat, D, qw);
    scatter_kernel<<<dim3(NBATCH, 2), 384>>>(D, out);
}

// round 17
// speedup vs baseline: 1.1651x; 1.1251x over previous
#include <cuda_runtime.h>
#include <math.h>

#define NA 48
#define NB 24
#define DIM 286
#define NBATCH 256
#define NMU 6
#define L5OFF 165

typedef unsigned long long u64;

// f32x2 packed helpers (FFMA2 — PTX-only on sm_103a)
__device__ __forceinline__ u64 pack2(float lo, float hi) {
    u64 r; asm("mov.b64 %0, {%1, %2};" : "=l"(r) : "f"(lo), "f"(hi)); return r;
}
__device__ __forceinline__ void unpack2(u64 v, float& lo, float& hi) {
    asm("mov.b64 {%0, %1}, %2;" : "=f"(lo), "=f"(hi) : "l"(v));
}
__device__ __forceinline__ u64 fma2(u64 a, u64 b, u64 c) {
    u64 r; asm("fma.rn.f32x2 %0, %1, %2, %3;" : "=l"(r) : "l"(a), "l"(b), "l"(c)); return r;
}
__device__ __forceinline__ u64 add2(u64 a, u64 b) {
    u64 r; asm("add.rn.f32x2 %0, %1, %2;" : "=l"(r) : "l"(a), "l"(b)); return r;
}
__device__ __forceinline__ float ex2a(float x) {
    float r; asm("ex2.approx.f32 %0, %1;" : "=f"(r) : "f"(x)); return r;
}
__device__ __forceinline__ float rcpa(float x) {
    float r; asm("rcp.approx.f32 %0, %1;" : "=f"(r) : "f"(x)); return r;
}
__device__ __forceinline__ float tanha(float x) {
    float r; asm("tanh.approx.f32 %0, %1;" : "=f"(r) : "f"(x)); return r;
}

// Scratch (static device globals; no allocation)
__device__ float g_c[NA * NMU];                // cos-like per (x, mu)
__device__ float g_s[NA * NMU];                // sin-like per (x, mu)
__device__ float g_act;                        // normalize2mom constant for tanh
__device__ float g_part[48];                   // partials for activation integral
__device__ float g_Q[NBATCH * NB * 144];       // Q forms [b][y][mn*4+c]

__constant__ int c_off[6] = {0, 1, 10, 35, 84, 165};

// ---------------------------------------------------------------------------
// ACT_CST integral partials: trapz of tanh(x)^2*N(0,1), 20001 pts, 48 CTAs.
// Accurate ex2/rcp tanh here (ACT_CST is a global scale — keep it ~1e-6).
// ---------------------------------------------------------------------------
__global__ void act_kernel() {
    const float L2E2 = 2.8853900817779268f;  // 2*log2(e)
    int tid = blockIdx.x * blockDim.x + threadIdx.x;  // 48*256 = 12288
    float sum = 0.f;
    for (int i = tid; i <= 20000; i += 12288) {
        float x = -12.f + (float)i * 1.2e-3f;
        float th = 1.0f - 2.0f * rcpa(ex2a(x * L2E2) + 1.0f);
        sum += th * th * __expf(-0.5f * x * x);
    }
    for (int o = 16; o; o >>= 1) sum += __shfl_down_sync(0xffffffffu, sum, o);
    __shared__ float ws[8];
    int w = threadIdx.x >> 5;
    if ((threadIdx.x & 31) == 0) ws[w] = sum;
    __syncthreads();
    if (threadIdx.x == 0) {
        float b = 0.f;
        for (int i = 0; i < 8; i++) b += ws[i];
        g_part[blockIdx.x] = b;
    }
}

// ---------------------------------------------------------------------------
// Prep: trig extraction (Ra5[x] = D5[x,0,0]*D5[0,0,0]^T/11) + act reduce.
// ---------------------------------------------------------------------------
__global__ void prep_kernel(const float* __restrict__ D) {
    int t = threadIdx.x;
    if (t < NA * NMU) {
        int x = t / NMU, mu = t % NMU;
        int p0 = 5 - mu, p1 = 5 + mu;
        const float* X = D + (size_t)x * NB * NA * DIM + L5OFF;
        const float* Z = D + L5OFF;
        float a00 = 0.f, a01 = 0.f, a10 = 0.f, a11 = 0.f;
        for (int k = 0; k < 11; k++) {
            float xp0 = X[p0 * 11 + k], xp1 = X[p1 * 11 + k];
            float zp0 = Z[p0 * 11 + k], zp1 = Z[p1 * 11 + k];
            a00 += xp0 * zp0; a01 += xp0 * zp1;
            a10 += xp1 * zp0; a11 += xp1 * zp1;
        }
        const float inv11 = 1.f / 11.f;
        g_c[t] = 0.5f * (a00 + a11) * inv11;
        g_s[t] = 0.5f * (a01 - a10) * inv11;
    }
    if (t == 0) {
        float tot = 0.f;
        for (int i = 0; i < 48; i++) tot += g_part[i];
        float I = tot * 1.2e-3f * 0.3989422804014327f;
        g_act = 1.0f / sqrtf(I);
    }
}

// ---------------------------------------------------------------------------
// Main (warp-autonomous, f32x2) — 55.8us-verified structure; single delta:
// activation via MUFU.TANH (tanh.approx) instead of ex2/rcp chain.
// T is prescaled by inv_s so tanh input is direct.
// ---------------------------------------------------------------------------
__global__ __launch_bounds__(128) void so3_main(const float* __restrict__ feat,
                                                const float* __restrict__ D,
                                                const float* __restrict__ qw) {
    const int b = blockIdx.x;
    const int t = threadIdx.x;
    const int w = t >> 5;
    const int lane = t & 31;
    const int y = blockIdx.y * 4 + w;

    __shared__ float sF[DIM];
    __shared__ __align__(16) u64 strigX2[NA][12];   // [x]: (c0,c0)(s0,s0)...(s5,s5)
    __shared__ float2 strigT[NMU][NA + 1];          // [mu][z], padded row
    __shared__ float4 sP4[4][36];                   // per-warp P forms (inv_s-scaled)
    __shared__ __align__(16) float2 sU[4][NMU][NA + 1];  // per-warp U

    for (int i = t; i < DIM; i += 128) sF[i] = feat[b * DIM + i];
    for (int i = t; i < NA * NMU; i += 128) {
        int x = i / NMU, mu = i % NMU;
        float c = g_c[i], s = g_s[i];
        strigX2[x][mu * 2 + 0] = pack2(c, c);
        strigX2[x][mu * 2 + 1] = pack2(s, s);
        strigT[mu][x] = make_float2(c, s);
    }
    __syncthreads();

    // K = inv_s: fold into P so synthesis output is tanh-ready
    const float K = 1.f / sqrtf(286.f);
    const float* By_g = D + (size_t)y * NA * DIM;   // D[0][y][0][:], L1/L2-hot

    // --- P forms (36 over 32 lanes; lanes 0-3 take a second form) ----------
#pragma unroll
    for (int rep = 0; rep < 2; rep++) {
        int f = lane + rep * 32;
        if (f < 36) {
            int mu = f / 6, nu = f % 6;
            float P00 = 0.f, P01 = 0.f, P10 = 0.f, P11 = 0.f;
            int l0 = mu > nu ? mu : nu;
            for (int l = l0; l <= 5; l++) {
                int dl = 2 * l + 1, off = c_off[l];
                int r0 = l - mu, r1 = l + mu, q0 = l - nu, q1 = l + nu;
                float F00 = sF[off + r0 * dl + q0], F01 = sF[off + r0 * dl + q1];
                float F10 = sF[off + r1 * dl + q0], F11 = sF[off + r1 * dl + q1];
                float B00 = By_g[off + r0 * dl + q0], B01 = By_g[off + r0 * dl + q1];
                float B10 = By_g[off + r1 * dl + q0], B11 = By_g[off + r1 * dl + q1];
                if (mu == 0) { F10 = F11 = 0.f; B10 = B11 = 0.f; }
                if (nu == 0) { F01 = F11 = 0.f; B01 = B11 = 0.f; }
                P00 +=  F00 * B00 + F01 * B01 + F10 * B10 + F11 * B11;
                P01 += -F00 * B01 + F01 * B00 - F10 * B11 + F11 * B10;
                P10 +=  F00 * B10 + F01 * B11 - F10 * B00 - F11 * B01;
                P11 += -F00 * B11 + F01 * B10 + F10 * B01 - F11 * B00;
            }
            sP4[w][f] = make_float4(P00 * K, P01 * K, P10 * K, P11 * K);
        }
    }
    __syncwarp();

    // --- T stage (packed f32x2: (z0,z1) lanes; in-register packs) ----------
    const int z0 = lane;
    const int z1 = 32 + (lane & 15);
    u64 T0p[6], T1p[6];
#pragma unroll
    for (int mu = 0; mu < 6; mu++) { T0p[mu] = 0ULL; T1p[mu] = 0ULL; }
#pragma unroll
    for (int nu = 0; nu < 6; nu++) {
        float2 ca = strigT[nu][z0];
        float2 cb = strigT[nu][z1];
        u64 cpk = pack2(ca.x, cb.x);
        u64 spk = pack2(ca.y, cb.y);
#pragma unroll
        for (int mu = 0; mu < 6; mu++) {
            float4 P = sP4[w][mu * 6 + nu];
            T0p[mu] = fma2(pack2(P.x, P.x), cpk, T0p[mu]);
            T0p[mu] = fma2(pack2(P.y, P.y), spk, T0p[mu]);
            T1p[mu] = fma2(pack2(P.z, P.z), cpk, T1p[mu]);
            T1p[mu] = fma2(pack2(P.w, P.w), spk, T1p[mu]);
        }
    }

    // --- fused synthesis + activation + U accumulation (all f32x2) ---------
    const float actq = g_act * qw[y];
    u64 U2[12];
#pragma unroll
    for (int k = 0; k < 12; k++) U2[k] = 0ULL;
#pragma unroll 4
    for (int x = 0; x < NA; x++) {
        const ulonglong2* cp = (const ulonglong2*)strigX2[x];
        ulonglong2 c01 = cp[0], c23 = cp[1], c45 = cp[2];
        ulonglong2 c67 = cp[3], c89 = cp[4], cAB = cp[5];
        // two-tree g accumulation (halves the serial FFMA2 chain)
        u64 gA = 0ULL, gB = 0ULL;
        gA = fma2(c01.x, T0p[0], gA); gA = fma2(c01.y, T1p[0], gA);
        gA = fma2(c23.x, T0p[1], gA); gA = fma2(c23.y, T1p[1], gA);
        gA = fma2(c45.x, T0p[2], gA); gA = fma2(c45.y, T1p[2], gA);
        gB = fma2(c67.x, T0p[3], gB); gB = fma2(c67.y, T1p[3], gB);
        gB = fma2(c89.x, T0p[4], gB); gB = fma2(c89.y, T1p[4], gB);
        gB = fma2(cAB.x, T0p[5], gB); gB = fma2(cAB.y, T1p[5], gB);
        u64 g2 = add2(gA, gB);
        float ga, gb;
        unpack2(g2, ga, gb);
        float ha = actq * tanha(ga);
        float hb = actq * tanha(gb);
        u64 h2 = pack2(ha, hb);
        U2[0]  = fma2(c01.x, h2, U2[0]);  U2[1]  = fma2(c01.y, h2, U2[1]);
        U2[2]  = fma2(c23.x, h2, U2[2]);  U2[3]  = fma2(c23.y, h2, U2[3]);
        U2[4]  = fma2(c45.x, h2, U2[4]);  U2[5]  = fma2(c45.y, h2, U2[5]);
        U2[6]  = fma2(c67.x, h2, U2[6]);  U2[7]  = fma2(c67.y, h2, U2[7]);
        U2[8]  = fma2(c89.x, h2, U2[8]);  U2[9]  = fma2(c89.y, h2, U2[9]);
        U2[10] = fma2(cAB.x, h2, U2[10]); U2[11] = fma2(cAB.y, h2, U2[11]);
    }
    {
        float U0[12], U1[12];
#pragma unroll
        for (int k = 0; k < 12; k++) unpack2(U2[k], U0[k], U1[k]);
#pragma unroll
        for (int mu = 0; mu < 6; mu++)
            sU[w][mu][z0] = make_float2(U0[2 * mu], U0[2 * mu + 1]);
        if (lane < 16) {
#pragma unroll
            for (int mu = 0; mu < 6; mu++)
                sU[w][mu][z1] = make_float2(U1[2 * mu], U1[2 * mu + 1]);
        }
    }
    __syncwarp();

    // --- Q forms part 1: forms 0..31, one per lane --------------------------
    {
        int mu = lane / 6, nu = lane % 6;
        u64 Qa = 0ULL, Qb = 0ULL;   // (Q00,Q10), (Q01,Q11)
        for (int z = 0; z < NA; z++) {
            u64 u2 = *(const u64*)&sU[w][mu][z];
            ulonglong2 cs = *(const ulonglong2*)&strigX2[z][2 * nu];
            Qa = fma2(u2, cs.x, Qa);
            Qb = fma2(u2, cs.y, Qb);
        }
        float Q00, Q10, Q01, Q11;
        unpack2(Qa, Q00, Q10);
        unpack2(Qb, Q01, Q11);
        *(float4*)(g_Q + ((size_t)(b * NB + y)) * 144 + lane * 4) =
            make_float4(Q00, Q01, Q10, Q11);
    }
    // --- Q forms part 2: forms 32..35 (mu=5, nu=2..5) over 8-lane groups ---
    {
        int grp = lane >> 3;
        int nu = 2 + grp;
        u64 Qa = 0ULL, Qb = 0ULL;
#pragma unroll
        for (int k = 0; k < 6; k++) {
            int z = (lane & 7) * 6 + k;
            u64 u2 = *(const u64*)&sU[w][5][z];
            ulonglong2 cs = *(const ulonglong2*)&strigX2[z][2 * nu];
            Qa = fma2(u2, cs.x, Qa);
            Qb = fma2(u2, cs.y, Qb);
        }
#pragma unroll
        for (int off = 1; off < 8; off <<= 1) {
            Qa = add2(Qa, __shfl_xor_sync(0xffffffffu, Qa, off));
            Qb = add2(Qb, __shfl_xor_sync(0xffffffffu, Qb, off));
        }
        if ((lane & 7) == 0) {
            float Q00, Q10, Q01, Q11;
            unpack2(Qa, Q00, Q10);
            unpack2(Qb, Q01, Q11);
            *(float4*)(g_Q + ((size_t)(b * NB + y)) * 144 + (32 + grp) * 4) =
                make_float4(Q00, Q01, Q10, Q11);
        }
    }
}

// ---------------------------------------------------------------------------
// Scatter (orbit-based): one thread computes ALL 4 outputs of a (mu,nu) orbit
// at level l, sharing the 4 B loads + 1 Q float4 per y across the outputs.
// grid (256 b, 2) x 384 threads = 48 orbit slots x 8 y-lanes (3 y each).
// ---------------------------------------------------------------------------
__global__ __launch_bounds__(384) void scatter_kernel(const float* __restrict__ D,
                                                      float* __restrict__ out) {
    const int b = blockIdx.x;
    const int tid = threadIdx.x;
    int task = blockIdx.y * 48 + (tid >> 3);   // orbit id 0..95
    const int h = tid & 7;                     // y-eighth (3 y each)
    const bool valid = task < 91;
    if (!valid) task = 90;

    int l = 0, rem = task;
    while (rem >= (l + 1) * (l + 1)) { rem -= (l + 1) * (l + 1); l++; }
    int mu = rem / (l + 1), nu = rem % (l + 1);
    int dl = 2 * l + 1, off = c_off[l];
    int r0 = l - mu, r1 = l + mu, q0 = l - nu, q1 = l + nu;
    int i00 = off + r0 * dl + q0, i01 = off + r0 * dl + q1;
    int i10 = off + r1 * dl + q0, i11 = off + r1 * dl + q1;
    int mn4 = (mu * 6 + nu) * 4;

    float o00 = 0.f, o01 = 0.f, o10 = 0.f, o11 = 0.f;
#pragma unroll
    for (int yv = 0; yv < 3; yv++) {
        int y = h * 3 + yv;
        float4 Q = *(const float4*)(g_Q + ((size_t)(b * NB + y)) * 144 + mn4);
        const float* By = D + (size_t)y * NA * DIM;
        float B00 = By[i00], B01 = By[i01], B10 = By[i10], B11 = By[i11];
        o00 += Q.x * B00 - Q.y * B01 + Q.z * B10 - Q.w * B11;
        o01 += Q.x * B01 + Q.y * B00 + Q.z * B11 + Q.w * B10;
        o10 += Q.x * B10 - Q.y * B11 - Q.z * B00 + Q.w * B01;
        o11 += Q.x * B11 + Q.y * B10 - Q.z * B01 - Q.w * B00;
    }
    u64 Pa = pack2(o00, o01), Pb = pack2(o10, o11);
#pragma unroll
    for (int o = 1; o < 8; o <<= 1) {
        Pa = add2(Pa, __shfl_xor_sync(0xffffffffu, Pa, o));
        Pb = add2(Pb, __shfl_xor_sync(0xffffffffu, Pb, o));
    }
    if (valid && h == 0) {
        unpack2(Pa, o00, o01);
        unpack2(Pb, o10, o11);
        const float ss = sqrtf(286.f);
        float* ob = out + (size_t)b * DIM;
        ob[i00] = ss * o00;
        if (nu > 0) ob[i01] = ss * o01;
        if (mu > 0) ob[i10] = ss * o10;
        if (mu > 0 && nu > 0) ob[i11] = ss * o11;
    }
}

extern "C" void kernel_launch(void* const* d_in, const int* in_sizes, int n_in,
                              void* d_out, int out_size) {
    const float* feat = (const float*)d_in[0];  // [256, 286]
    const float* D    = (const float*)d_in[1];  // [48, 24, 48, 286]
    const float* qw   = (const float*)d_in[2];  // [24]
    float* out        = (float*)d_out;          // [256, 286]

    act_kernel<<<48, 256>>>();
    prep_kernel<<<1, 512>>>(D);
    so3_main<<<dim3(NBATCH, 6), 128>>>(feat, D, qw);
    scatter_kernel<<<dim3(NBATCH, 2), 384>>>(D, out);
}